// round 4
// baseline (speedup 1.0000x reference)
#include <cuda_runtime.h>
#include <cstdint>

// out[b,t,:] = [ features[b,t,:] @ W^T + bias , pe(positions[t]) ]
// B=16384, T=64, F=16, Dh=128. Output = 32768 contiguous 32KB "units".
//
// Per block: 3-deep pipeline of 32KB staging tiles, TMA bulk stores.
// pe halves written once per buffer at block start (computed in-kernel,
// double precision). W held in registers as f32x2 pairs.

#define T_DIM 64
#define F_DIM 16
#define DH    128
#define GRID  296          // even -> unit parity fixed per block
#define TPB   256
#define NBUF  3
#define STG_FLOATS  8192   // 32 rows * 256 cols
#define FFB_FLOATS  512    // 32 rows * 16
#define SMEM_BYTES  (NBUF * (STG_FLOATS + FFB_FLOATS) * 4)   // 104448

__device__ __forceinline__ uint32_t smem_u32(const void* p)
{
    return (uint32_t)__cvta_generic_to_shared(p);
}
__device__ __forceinline__ void cp16(uint32_t dst, const void* src)
{
    asm volatile("cp.async.cg.shared.global [%0], [%1], 16;" :: "r"(dst), "l"(src));
}
__device__ __forceinline__ unsigned long long pack2(float a, float b)
{
    unsigned long long r;
    asm("mov.b64 %0, {%1, %2};" : "=l"(r) : "f"(a), "f"(b));
    return r;
}
__device__ __forceinline__ void fma2(unsigned long long& d,
                                     unsigned long long a, unsigned long long b)
{
    asm("fma.rn.f32x2 %0, %1, %2, %0;" : "+l"(d) : "l"(a), "l"(b));
}

__global__ __launch_bounds__(TPB, 2) void obs_embed_kernel(
    const float* __restrict__ features,   // [B,64,16]
    const float* __restrict__ W,          // [128,16]
    const float* __restrict__ bias,       // [128]
    const int*   __restrict__ positions,  // [64]
    float*       __restrict__ out,        // [B,64,256]
    int nUnits)                           // B*2
{
    extern __shared__ float smem[];
    float* stg = smem;                       // [NBUF][32][256]
    float* ffb = smem + NBUF * STG_FLOATS;   // [NBUF][32][16]

    const int tid  = threadIdx.x;
    const int lane = tid & 31;
    const int warp = tid >> 5;

    const int t0 = (blockIdx.x & 1) * 32;    // unit parity fixed (GRID even)

    int u = blockIdx.x;

    // Prologue: prefetch features for iters 0 and 1 (distance-2 pipeline).
    #pragma unroll
    for (int i = 0; i < 2; ++i) {
        int up = u + i * GRID;
        if (up < nUnits && lane < 16)
            cp16(smem_u32(ffb + i * FFB_FLOATS + warp * 64 + lane * 4),
                 features + (size_t)up * 512 + warp * 64 + lane * 4);
        asm volatile("cp.async.commit_group;");
    }

    // pe halves of all NBUF staging buffers: constant for this block.
    // 32 rows x 64 (sin,cos) pairs; 8 pairs per thread, double precision.
    for (int idx = tid; idx < 32 * 64; idx += TPB) {
        int r = idx >> 6, j = idx & 63;
        double pos = (double)positions[t0 + r];
        double ang = pos * exp2(-(double)j * (13.287712379549449 / 32.0));
        double s, c;
        sincos(ang, &s, &c);
        #pragma unroll
        for (int bfi = 0; bfi < NBUF; ++bfi) {
            stg[bfi * STG_FLOATS + r * 256 + DH + 2 * j]     = (float)s;
            stg[bfi * STG_FLOATS + r * 256 + DH + 2 * j + 1] = (float)c;
        }
    }

    // W into packed registers. Lane owns output cols d = 4*lane + {0..3}.
    unsigned long long wp0[16], wp1[16];
    {
        const float4* Wv = reinterpret_cast<const float4*>(W);
        #pragma unroll
        for (int q = 0; q < 4; ++q) {
            float4 w0 = Wv[(4 * lane + 0) * 4 + q];
            float4 w1 = Wv[(4 * lane + 1) * 4 + q];
            float4 w2 = Wv[(4 * lane + 2) * 4 + q];
            float4 w3 = Wv[(4 * lane + 3) * 4 + q];
            wp0[4*q+0] = pack2(w0.x, w1.x);  wp1[4*q+0] = pack2(w2.x, w3.x);
            wp0[4*q+1] = pack2(w0.y, w1.y);  wp1[4*q+1] = pack2(w2.y, w3.y);
            wp0[4*q+2] = pack2(w0.z, w1.z);  wp1[4*q+2] = pack2(w2.z, w3.z);
            wp0[4*q+3] = pack2(w0.w, w1.w);  wp1[4*q+3] = pack2(w2.w, w3.w);
        }
    }
    const unsigned long long bp0 = pack2(bias[4 * lane + 0], bias[4 * lane + 1]);
    const unsigned long long bp1 = pack2(bias[4 * lane + 2], bias[4 * lane + 3]);

    int p = 0;
    for (; u < nUnits; u += GRID, p = (p + 1 == NBUF) ? 0 : p + 1) {
        // Prefetch features 2 iterations ahead (always commit: group parity).
        {
            int un = u + 2 * GRID;
            int fp = (p + 2 >= NBUF) ? p + 2 - NBUF : p + 2;
            if (un < nUnits && lane < 16)
                cp16(smem_u32(ffb + fp * FFB_FLOATS + warp * 64 + lane * 4),
                     features + (size_t)un * 512 + warp * 64 + lane * 4);
            asm volatile("cp.async.commit_group;");
        }

        // Buffer p was stored 3 iterations ago: ensure TMA finished reading it.
        if (tid == 0) asm volatile("cp.async.bulk.wait_group.read %0;" :: "n"(NBUF - 1));
        __syncthreads();

        // Current unit's features (committed 2 iters ago) ready.
        asm volatile("cp.async.wait_group 2;");
        __syncwarp();

        float* stgp = stg + p * STG_FLOATS;
        const float* fcur = ffb + p * FFB_FLOATS + warp * 64;  // warp's 4 rows

        #pragma unroll
        for (int rr = 0; rr < 4; ++rr) {
            const float4* frow = reinterpret_cast<const float4*>(fcur + rr * 16);
            unsigned long long a0 = bp0, a1 = bp1;
            #pragma unroll
            for (int q = 0; q < 4; ++q) {
                const float4 f = frow[q];   // broadcast LDS, conflict-free
                unsigned long long ff;
                ff = pack2(f.x, f.x); fma2(a0, ff, wp0[4*q+0]); fma2(a1, ff, wp1[4*q+0]);
                ff = pack2(f.y, f.y); fma2(a0, ff, wp0[4*q+1]); fma2(a1, ff, wp1[4*q+1]);
                ff = pack2(f.z, f.z); fma2(a0, ff, wp0[4*q+2]); fma2(a1, ff, wp1[4*q+2]);
                ff = pack2(f.w, f.w); fma2(a0, ff, wp0[4*q+3]); fma2(a1, ff, wp1[4*q+3]);
            }
            uint32_t sa = smem_u32(stgp + (warp * 4 + rr) * 256 + lane * 4);
            asm volatile("st.shared.v2.u64 [%0], {%1, %2};"
                         :: "r"(sa), "l"(a0), "l"(a1));
        }
        __syncthreads();

        if (tid == 0) {
            asm volatile("fence.proxy.async.shared::cta;");
            asm volatile(
                "cp.async.bulk.global.shared::cta.bulk_group [%0], [%1], %2;"
                :: "l"(out + (size_t)u * STG_FLOATS),
                   "r"(smem_u32(stgp)), "r"(32768) : "memory");
            asm volatile("cp.async.bulk.commit_group;");
        }
    }
    // Drain outstanding bulk stores before CTA exit (smem must stay live).
    asm volatile("cp.async.bulk.wait_group 0;");
    __syncthreads();
}

extern "C" void kernel_launch(void* const* d_in, const int* in_sizes, int n_in,
                              void* d_out, int out_size)
{
    const float* features  = (const float*)d_in[0];
    const float* W         = (const float*)d_in[1];
    const float* bias      = (const float*)d_in[2];
    const int*   positions = (const int*)d_in[3];
    float* out = (float*)d_out;

    const int B = in_sizes[0] / (T_DIM * F_DIM);

    cudaFuncSetAttribute(obs_embed_kernel,
                         cudaFuncAttributeMaxDynamicSharedMemorySize, SMEM_BYTES);

    obs_embed_kernel<<<GRID, TPB, SMEM_BYTES>>>(features, W, bias, positions,
                                                out, B * 2);
}

// round 5
// speedup vs baseline: 1.0982x; 1.0982x over previous
#include <cuda_runtime.h>
#include <cstdint>

// out[b,t,:] = [ features[b,t,:] @ W^T + bias , pe(positions[t]) ]
// B=16384, T=64, F=16, Dh=128. Output = 32768 contiguous 32KB "units".
//
// Per block: 3-deep pipeline of 32KB staging tiles. ONE __syncthreads per
// iteration; TMA bulk store for iter i issued at top of iter i+1 (overlapped
// with compute). pe computed once per block with DP range-reduction +
// float sincosf (no heavy FP64). W in registers as f32x2 pairs.

#define T_DIM 64
#define F_DIM 16
#define DH    128
#define GRID  296          // even -> unit parity fixed per block
#define TPB   256
#define NBUF  3
#define STG_FLOATS  8192   // 32 rows * 256 cols
#define FFB_FLOATS  512    // 32 rows * 16
#define SMEM_BYTES  (NBUF * (STG_FLOATS + FFB_FLOATS) * 4)   // 104448

__device__ __forceinline__ uint32_t smem_u32(const void* p)
{
    return (uint32_t)__cvta_generic_to_shared(p);
}
__device__ __forceinline__ void cp16(uint32_t dst, const void* src)
{
    asm volatile("cp.async.cg.shared.global [%0], [%1], 16;" :: "r"(dst), "l"(src));
}
__device__ __forceinline__ unsigned long long pack2(float a, float b)
{
    unsigned long long r;
    asm("mov.b64 %0, {%1, %2};" : "=l"(r) : "f"(a), "f"(b));
    return r;
}
__device__ __forceinline__ void fma2(unsigned long long& d,
                                     unsigned long long a, unsigned long long b)
{
    asm("fma.rn.f32x2 %0, %1, %2, %0;" : "+l"(d) : "l"(a), "l"(b));
}

__global__ __launch_bounds__(TPB, 2) void obs_embed_kernel(
    const float* __restrict__ features,   // [B,64,16]
    const float* __restrict__ W,          // [128,16]
    const float* __restrict__ bias,       // [128]
    const int*   __restrict__ positions,  // [64]
    float*       __restrict__ out,        // [B,64,256]
    int nUnits)                           // B*2
{
    extern __shared__ float smem[];
    float* stg = smem;                       // [NBUF][32][256]
    float* ffb = smem + NBUF * STG_FLOATS;   // [NBUF][32][16]

    const int tid  = threadIdx.x;
    const int lane = tid & 31;
    const int warp = tid >> 5;

    const int t0 = (blockIdx.x & 1) * 32;    // unit parity fixed (GRID even)

    int u = blockIdx.x;

    // Prologue: prefetch features for iters 0 and 1 (distance-2 pipeline).
    #pragma unroll
    for (int i = 0; i < 2; ++i) {
        int up = u + i * GRID;
        if (up < nUnits && lane < 16)
            cp16(smem_u32(ffb + i * FFB_FLOATS + warp * 64 + lane * 4),
                 features + (size_t)up * 512 + warp * 64 + lane * 4);
        asm volatile("cp.async.commit_group;");
    }

    // pe halves of all NBUF staging buffers (constant for this block).
    // angle in double with manual 2*pi reduction (3 DP ops), then sincosf.
    for (int idx = tid; idx < 32 * 64; idx += TPB) {
        int r = idx >> 6, j = idx & 63;
        double pos = (double)positions[t0 + r];
        double ang = pos * exp2(-(double)j * (13.287712379549449 / 32.0));
        double k   = rint(ang * 0.15915494309189535);       // 1/(2*pi)
        double red = fma(-k, 6.283185307179586, ang);       // |red| <= pi
        float s, c;
        sincosf((float)red, &s, &c);
        #pragma unroll
        for (int bfi = 0; bfi < NBUF; ++bfi) {
            stg[bfi * STG_FLOATS + r * 256 + DH + 2 * j]     = s;
            stg[bfi * STG_FLOATS + r * 256 + DH + 2 * j + 1] = c;
        }
    }

    // W into packed registers. Lane owns output cols d = 4*lane + {0..3}.
    unsigned long long wp0[16], wp1[16];
    {
        const float4* Wv = reinterpret_cast<const float4*>(W);
        #pragma unroll
        for (int q = 0; q < 4; ++q) {
            float4 w0 = Wv[(4 * lane + 0) * 4 + q];
            float4 w1 = Wv[(4 * lane + 1) * 4 + q];
            float4 w2 = Wv[(4 * lane + 2) * 4 + q];
            float4 w3 = Wv[(4 * lane + 3) * 4 + q];
            wp0[4*q+0] = pack2(w0.x, w1.x);  wp1[4*q+0] = pack2(w2.x, w3.x);
            wp0[4*q+1] = pack2(w0.y, w1.y);  wp1[4*q+1] = pack2(w2.y, w3.y);
            wp0[4*q+2] = pack2(w0.z, w1.z);  wp1[4*q+2] = pack2(w2.z, w3.z);
            wp0[4*q+3] = pack2(w0.w, w1.w);  wp1[4*q+3] = pack2(w2.w, w3.w);
        }
    }
    const unsigned long long bp0 = pack2(bias[4 * lane + 0], bias[4 * lane + 1]);
    const unsigned long long bp1 = pack2(bias[4 * lane + 2], bias[4 * lane + 3]);

    bool   have_prev = false;
    float* prev_gl = nullptr;
    const float* prev_sm = nullptr;

    int p = 0;
    for (; u < nUnits; u += GRID, p = (p + 1 == NBUF) ? 0 : p + 1) {
        // Prefetch features 2 iterations ahead (always commit: group count).
        {
            int un = u + 2 * GRID;
            int fp = (p + 2 >= NBUF) ? p + 2 - NBUF : p + 2;
            if (un < nUnits && lane < 16)
                cp16(smem_u32(ffb + fp * FFB_FLOATS + warp * 64 + lane * 4),
                     features + (size_t)un * 512 + warp * 64 + lane * 4);
            asm volatile("cp.async.commit_group;");
        }

        // Buffer p reused now; its store was issued 2 iters ago. Allow 1
        // outstanding store group -> buffer p's group must be drained.
        if (tid == 0) asm volatile("cp.async.bulk.wait_group.read 1;");

        // The single barrier: publishes previous iter's STS to tid0, and
        // publishes buffer-p-drained to all warps.
        __syncthreads();

        // Issue previous iteration's bulk store (overlaps this iter's compute).
        if (tid == 0 && have_prev) {
            asm volatile("fence.proxy.async.shared::cta;");
            asm volatile(
                "cp.async.bulk.global.shared::cta.bulk_group [%0], [%1], %2;"
                :: "l"(prev_gl), "r"(smem_u32(prev_sm)), "r"(32768) : "memory");
            asm volatile("cp.async.bulk.commit_group;");
        }

        // This iter's features (committed 2 iters ago) ready.
        asm volatile("cp.async.wait_group 2;");
        __syncwarp();

        float* stgp = stg + p * STG_FLOATS;
        const float* fcur = ffb + p * FFB_FLOATS + warp * 64;  // warp's 4 rows

        #pragma unroll
        for (int rr = 0; rr < 4; ++rr) {
            const float4* frow = reinterpret_cast<const float4*>(fcur + rr * 16);
            unsigned long long a0 = bp0, a1 = bp1;
            #pragma unroll
            for (int q = 0; q < 4; ++q) {
                const float4 f = frow[q];   // broadcast LDS, conflict-free
                unsigned long long ff;
                ff = pack2(f.x, f.x); fma2(a0, ff, wp0[4*q+0]); fma2(a1, ff, wp1[4*q+0]);
                ff = pack2(f.y, f.y); fma2(a0, ff, wp0[4*q+1]); fma2(a1, ff, wp1[4*q+1]);
                ff = pack2(f.z, f.z); fma2(a0, ff, wp0[4*q+2]); fma2(a1, ff, wp1[4*q+2]);
                ff = pack2(f.w, f.w); fma2(a0, ff, wp0[4*q+3]); fma2(a1, ff, wp1[4*q+3]);
            }
            uint32_t sa = smem_u32(stgp + (warp * 4 + rr) * 256 + lane * 4);
            asm volatile("st.shared.v2.u64 [%0], {%1, %2};"
                         :: "r"(sa), "l"(a0), "l"(a1));
        }

        have_prev = true;
        prev_gl = out + (size_t)u * STG_FLOATS;
        prev_sm = stgp;
    }

    // Epilogue: store the final tile, then drain before CTA exit.
    __syncthreads();
    if (tid == 0 && have_prev) {
        asm volatile("fence.proxy.async.shared::cta;");
        asm volatile(
            "cp.async.bulk.global.shared::cta.bulk_group [%0], [%1], %2;"
            :: "l"(prev_gl), "r"(smem_u32(prev_sm)), "r"(32768) : "memory");
        asm volatile("cp.async.bulk.commit_group;");
    }
    asm volatile("cp.async.bulk.wait_group 0;");   // empty for tid!=0
    __syncthreads();                                // keep smem live for TMA
}

extern "C" void kernel_launch(void* const* d_in, const int* in_sizes, int n_in,
                              void* d_out, int out_size)
{
    const float* features  = (const float*)d_in[0];
    const float* W         = (const float*)d_in[1];
    const float* bias      = (const float*)d_in[2];
    const int*   positions = (const int*)d_in[3];
    float* out = (float*)d_out;

    const int B = in_sizes[0] / (T_DIM * F_DIM);

    cudaFuncSetAttribute(obs_embed_kernel,
                         cudaFuncAttributeMaxDynamicSharedMemorySize, SMEM_BYTES);

    obs_embed_kernel<<<GRID, TPB, SMEM_BYTES>>>(features, W, bias, positions,
                                                out, B * 2);
}